// round 11
// baseline (speedup 1.0000x reference)
#include <cuda_runtime.h>
#include <cuda_bf16.h>

typedef unsigned long long ull;

#define NC 173
#define NL 400
#define NB 64
#define BPB 4                   // batches per tower block
#define FEAT_PER_C 320          // 32 ch * 10 pool
#define NFEAT (NC * FEAT_PER_C) // 55360
#define KSPLIT 160
#define KCH (NFEAT / KSPLIT)    // 346

#define Y1S 418                 // y1 row stride (left halo 7; 418 mod 32 = 2)
#define XSS 416                 // xs row stride

__device__ float  g_feat[NB * NFEAT];          // pooled features [b][55360]
__device__ float  g_part[KSPLIT * NB * 128];   // FC1 partials [ks][b][j]
__device__ float  g_w1f[NC * 144];             // BN1-folded conv1 weights
__device__ float  g_t1 [NC * 16];              // BN1-folded bias
__device__ __align__(16) float2 g_w2i[NC * 1792]; // BN2-folded interleaved conv2 weights
__device__ float2 g_t2 [NC * 16];              // BN2-folded bias pairs

// ---------- packed f32x2 helpers (sm_103a FFMA2) ----------
__device__ __forceinline__ ull fma2(ull a, ull b, ull c) {
    ull d;
    asm("fma.rn.f32x2 %0, %1, %2, %3;" : "=l"(d) : "l"(a), "l"(b), "l"(c));
    return d;
}
__device__ __forceinline__ ull add2(ull a, ull b) {
    ull d;
    asm("add.rn.f32x2 %0, %1, %2;" : "=l"(d) : "l"(a), "l"(b));
    return d;
}
__device__ __forceinline__ ull pack2(float lo, float hi) {
    ull d;
    asm("mov.b64 %0, {%1, %2};" : "=l"(d) : "f"(lo), "f"(hi));
    return d;
}
__device__ __forceinline__ float2 unpack2(ull v) {
    float2 r;
    asm("mov.b64 {%0, %1}, %2;" : "=f"(r.x), "=f"(r.y) : "l"(v));
    return r;
}

// =====================================================================
// Kernel P: per-channel weight prep (BN fold + conv2 pair interleave)
// =====================================================================
__global__ __launch_bounds__(256) void prep_kernel(
    const float* __restrict__ w1g, const float* __restrict__ b1,
    const float* __restrict__ g1,  const float* __restrict__ beta1,
    const float* __restrict__ m1,  const float* __restrict__ v1,
    const float* __restrict__ w2g, const float* __restrict__ b2,
    const float* __restrict__ g2,  const float* __restrict__ beta2,
    const float* __restrict__ m2,  const float* __restrict__ v2)
{
    __shared__ float s1s[16], s2s[32], t2s[32];
    const int c = blockIdx.x, tid = threadIdx.x;

    if (tid < 16) {
        int cf = c * 16 + tid;
        float s = g1[cf] * rsqrtf(v1[cf] + 1e-5f);
        s1s[tid] = s;
        g_t1[cf] = s * (b1[cf] - m1[cf]) + beta1[cf];
    }
    if (tid >= 32 && tid < 64) {
        int o = tid - 32, co = c * 32 + o;
        float s = g2[co] * rsqrtf(v2[co] + 1e-5f);
        s2s[o] = s;
        t2s[o] = s * (b2[co] - m2[co]) + beta2[co];
    }
    __syncthreads();

    if (tid < 144)
        g_w1f[c * 144 + tid] = w1g[c * 144 + tid] * s1s[tid / 9];
    if (tid >= 144 && tid < 160) {
        int pr = tid - 144;
        g_t2[c * 16 + pr] = make_float2(t2s[2 * pr], t2s[2 * pr + 1]);
    }
    // interleave: g_w2i[c][(i*7+k)*16 + pr] = {s*w2[o=2pr], s*w2[o=2pr+1]}
    const float* wc = w2g + c * 3584;     // [o][i][k], o-stride 112
    for (int idx = tid; idx < 1792; idx += 256) {
        int pr = idx & 15, ik = idx >> 4;
        int i = ik / 7, k = ik - i * 7;
        int o0 = 2 * pr;
        g_w2i[c * 1792 + idx] = make_float2(wc[o0 * 112 + i * 7 + k] * s2s[o0],
                                            wc[(o0 + 1) * 112 + i * 7 + k] * s2s[o0 + 1]);
    }
}

// =====================================================================
// conv1 for one batch row: thread = (f, tile); weights in registers,
// x window via LDS.128, 20 outputs per thread.
// =====================================================================
__device__ __forceinline__ void conv1_batch(
    const float* __restrict__ xb,      // xs row (with pad-4 halo), 416 floats
    const float* __restrict__ w1s,     // 16 x 9 folded weights
    const float* __restrict__ t1s,     // 16 folded biases
    float* __restrict__ y1s, int tid)
{
    const int f = tid & 15;
    const int t0 = (tid >> 4) * 20;    // 0,20,...,380

    float w[9];
#pragma unroll
    for (int k = 0; k < 9; ++k) w[k] = w1s[f * 9 + k];
    const float bias = t1s[f];

    float xv[28];
    const float4* xb4 = reinterpret_cast<const float4*>(xb + t0);  // 16B aligned
#pragma unroll
    for (int m = 0; m < 7; ++m) {
        float4 v = xb4[m];
        xv[4 * m] = v.x; xv[4 * m + 1] = v.y;
        xv[4 * m + 2] = v.z; xv[4 * m + 3] = v.w;
    }

    float* ydst = &y1s[f * Y1S + 7 + t0];
#pragma unroll
    for (int t = 0; t < 20; ++t) {
        float a = 0.f;
#pragma unroll
        for (int k = 0; k < 9; ++k) a = fmaf(w[k], xv[t + k], a);
        ydst[t] = fmaxf(a + bias, 0.f);
    }
}

// =====================================================================
// Kernel A: one block per (c, 4 batches), 320 threads.
// Stage weights once; loop 4 batches: conv1 -> conv2 (FFMA2) -> pool.
// =====================================================================
__global__ __launch_bounds__(320, 2) void tower_kernel(const float* __restrict__ x)
{
    __shared__ __align__(16) float xs[BPB * XSS];     // 4 x rows, pad-4 halo
    __shared__ float w1s[144];                        // folded 16x9
    __shared__ float t1s[16];
    __shared__ __align__(16) float y1s[16 * Y1S];     // conv1 out, halo-7 left
    __shared__ __align__(16) float2 w2p[16 * 7 * 16]; // [i][k][opair]
    __shared__ float2 t2p[16];
    __shared__ __align__(16) float4 pool_p[FEAT_PER_C]; // [ch*10+pw] x 4 subs

    const int blk = blockIdx.x;
    const int bg = blk / NC, c = blk - bg * NC;
    const int b0 = bg * BPB;
    const int tid = threadIdx.x;

    // ---------------- phase 0: stage once per block ----------------
    for (int idx = tid; idx < BPB * 408; idx += 320) {
        int r = idx / 408, j = idx - r * 408;
        xs[r * XSS + j] = (j >= 4 && j < 404)
                        ? x[((b0 + r) * NC + c) * NL + (j - 4)] : 0.f;
    }
    if (tid < 144) w1s[tid] = g_w1f[c * 144 + tid];
    if (tid >= 144 && tid < 160) t1s[tid - 144] = g_t1[c * 16 + tid - 144];
    if (tid >= 160 && tid < 176) t2p[tid - 160] = g_t2[c * 16 + tid - 160];
    {   // w2p copy: 1792 float2 = 896 float4
        const float4* src = reinterpret_cast<const float4*>(g_w2i + c * 1792);
        float4* dst = reinterpret_cast<float4*>(w2p);
        for (int idx = tid; idx < 896; idx += 320) dst[idx] = src[idx];
    }
    if (tid < 288) {     // zero y1 halos once: cols 0..6 and 407..417 (18/row)
        int i = tid / 18, jj = tid - i * 18;
        y1s[i * Y1S + (jj < 7 ? jj : 400 + jj)] = 0.f;
    }
    __syncthreads();

    // ---------------- conv1 for batch 0 ----------------
    conv1_batch(&xs[0], w1s, t1s, y1s, tid);
    __syncthreads();

#pragma unroll 1
    for (int bb = 0; bb < BPB; ++bb) {
        // ---- conv2 (32 x 400) FFMA2 + bias + ReLU + pool partials ----
        {
            const int g  = tid >> 3;       // 0..39: position tile of 10
            const int cg = tid & 7;        // pairs {2cg,2cg+1} -> ch 4cg..4cg+3
            const int t0 = g * 10;

            ull acc[2][10];
#pragma unroll
            for (int p = 0; p < 2; ++p)
#pragma unroll
                for (int t = 0; t < 10; ++t) acc[p][t] = 0ull;

            const ulonglong2* w2u2 = reinterpret_cast<const ulonglong2*>(w2p);

#pragma unroll 1
            for (int i = 0; i < 16; ++i) {
                const float2* ybase =
                    reinterpret_cast<const float2*>(&y1s[i * Y1S + t0 + 4]);
                ull yp[16];
#pragma unroll
                for (int m = 0; m < 8; ++m) {
                    float2 a = ybase[m];
                    yp[2 * m]     = pack2(a.x, a.x);
                    yp[2 * m + 1] = pack2(a.y, a.y);
                }
                const ulonglong2* wr = w2u2 + i * 56 + cg;   // stride 8 per k
#pragma unroll
                for (int k = 0; k < 7; ++k) {
                    ulonglong2 w = wr[k * 8];
#pragma unroll
                    for (int t = 0; t < 10; ++t) {
                        acc[0][t] = fma2(w.x, yp[t + k], acc[0][t]);
                        acc[1][t] = fma2(w.y, yp[t + k], acc[1][t]);
                    }
                }
            }

            // epilogue: +bias, ReLU, pool 10 positions, scatter partial
            const ull* t2u = reinterpret_cast<const ull*>(t2p);
            const int pw = g >> 2;
            const int sub = g & 3;
            float* poolf = reinterpret_cast<float*>(pool_p);
#pragma unroll
            for (int p = 0; p < 2; ++p) {
                int pr = 2 * cg + p;
                ull bi = t2u[pr];
                float mlo = 0.f, mhi = 0.f;
#pragma unroll
                for (int t = 0; t < 10; ++t) {
                    float2 v = unpack2(add2(acc[p][t], bi));
                    mlo = fmaxf(mlo, v.x);
                    mhi = fmaxf(mhi, v.y);
                }
                poolf[((2 * pr) * 10 + pw) * 4 + sub]     = mlo;
                poolf[((2 * pr + 1) * 10 + pw) * 4 + sub] = mhi;
            }
        }
        __syncthreads();

        // ---- writeback(bb) + conv1(bb+1) between the same pair of syncs ----
        {
            float4 v = pool_p[tid];               // FEAT_PER_C == blockDim == 320
            g_feat[(b0 + bb) * NFEAT + c * FEAT_PER_C + tid] =
                fmaxf(fmaxf(v.x, v.y), fmaxf(v.z, v.w));
        }
        if (bb + 1 < BPB) {
            conv1_batch(&xs[(bb + 1) * XSS], w1s, t1s, y1s, tid);
            __syncthreads();
        }
    }
}

// =====================================================================
// Kernel B: FC1 outer-product, FFMA2, K-split partials
// grid (2 j-tiles of 64, KSPLIT), 256 threads; thread = 4b x 4j
// =====================================================================
__global__ __launch_bounds__(256) void fc1_kernel(const float* __restrict__ wc1)
{
    __shared__ __align__(16) float fs[64 * 66];
    __shared__ __align__(16) float ws[64 * 66];

    const int jt = blockIdx.x, ks = blockIdx.y;
    const int tid = threadIdx.x;
    const int bq = tid >> 4;        // 0..15 -> b rows {bq, bq+16, bq+32, bq+48}
    const int jq = tid & 15;        // 0..15 -> j rows {jq, jq+16, jq+32, jq+48}
    const int kbeg = ks * KCH, kend = kbeg + KCH;

    ull acc[4][4];
#pragma unroll
    for (int rb = 0; rb < 4; ++rb)
#pragma unroll
        for (int rj = 0; rj < 4; ++rj) acc[rb][rj] = 0ull;

    for (int k0 = kbeg; k0 < kend; k0 += 64) {
#pragma unroll
        for (int l = 0; l < 16; ++l) {
            int idx = tid + l * 256;
            int r = idx >> 6, cc = idx & 63;
            int k = k0 + cc;
            fs[r * 66 + cc] = (k < kend) ? g_feat[r * NFEAT + k] : 0.f;
            ws[r * 66 + cc] = (k < kend) ? wc1[(jt * 64 + r) * NFEAT + k] : 0.f;
        }
        __syncthreads();

        const ull* fs2 = reinterpret_cast<const ull*>(fs);
        const ull* ws2 = reinterpret_cast<const ull*>(ws);
#pragma unroll 4
        for (int cc2 = 0; cc2 < 32; ++cc2) {
            ull fv[4], wv[4];
#pragma unroll
            for (int r = 0; r < 4; ++r) fv[r] = fs2[(bq + 16 * r) * 33 + cc2];
#pragma unroll
            for (int r = 0; r < 4; ++r) wv[r] = ws2[(jq + 16 * r) * 33 + cc2];
#pragma unroll
            for (int rb = 0; rb < 4; ++rb)
#pragma unroll
                for (int rj = 0; rj < 4; ++rj)
                    acc[rb][rj] = fma2(fv[rb], wv[rj], acc[rb][rj]);
        }
        __syncthreads();
    }

#pragma unroll
    for (int rb = 0; rb < 4; ++rb) {
        int b = bq + 16 * rb;
#pragma unroll
        for (int rj = 0; rj < 4; ++rj) {
            int j = jt * 64 + jq + 16 * rj;
            float2 v = unpack2(acc[rb][rj]);
            g_part[(ks * NB + b) * 128 + j] = v.x + v.y;
        }
    }
}

// =====================================================================
// Kernel C: reduce partials (8-way split), bias1, ReLU, FC2
// =====================================================================
__global__ __launch_bounds__(1024) void fc2_kernel(
    const float* __restrict__ bc1, const float* __restrict__ wc2,
    const float* __restrict__ bc2, float* __restrict__ out)
{
    __shared__ float part[8][128];
    __shared__ float red[4];
    const int b = blockIdx.x;
    const int j = threadIdx.x & 127, r = threadIdx.x >> 7;   // r 0..7

    float s = 0.f;
#pragma unroll 5
    for (int ks = r; ks < KSPLIT; ks += 8)
        s += g_part[(ks * NB + b) * 128 + j];
    part[r][j] = s;
    __syncthreads();

    if (threadIdx.x < 128) {
        float t = bc1[j];
#pragma unroll
        for (int r2 = 0; r2 < 8; ++r2) t += part[r2][j];
        float v = fmaxf(t, 0.f) * wc2[j];
#pragma unroll
        for (int o = 16; o > 0; o >>= 1)
            v += __shfl_down_sync(0xffffffffu, v, o);
        if ((j & 31) == 0) red[j >> 5] = v;
    }
    __syncthreads();
    if (threadIdx.x == 0) out[b] = red[0] + red[1] + red[2] + red[3] + bc2[0];
}

// =====================================================================
extern "C" void kernel_launch(void* const* d_in, const int* in_sizes, int n_in,
                              void* d_out, int out_size)
{
    const float* x     = (const float*)d_in[0];
    const float* w1    = (const float*)d_in[1];
    const float* b1    = (const float*)d_in[2];
    const float* g1    = (const float*)d_in[3];
    const float* beta1 = (const float*)d_in[4];
    const float* m1    = (const float*)d_in[5];
    const float* v1    = (const float*)d_in[6];
    const float* w2    = (const float*)d_in[7];
    const float* b2    = (const float*)d_in[8];
    const float* g2    = (const float*)d_in[9];
    const float* beta2 = (const float*)d_in[10];
    const float* m2    = (const float*)d_in[11];
    const float* v2    = (const float*)d_in[12];
    const float* wc1   = (const float*)d_in[13];
    const float* bc1   = (const float*)d_in[14];
    const float* wc2   = (const float*)d_in[15];
    const float* bc2   = (const float*)d_in[16];
    float* out = (float*)d_out;

    prep_kernel<<<NC, 256>>>(w1, b1, g1, beta1, m1, v1,
                             w2, b2, g2, beta2, m2, v2);
    tower_kernel<<<NC * (NB / BPB), 320>>>(x);
    fc1_kernel<<<dim3(2, KSPLIT), 256>>>(wc1);
    fc2_kernel<<<NB, 1024>>>(bc1, wc2, bc2, out);
}

// round 14
// speedup vs baseline: 1.2899x; 1.2899x over previous
#include <cuda_runtime.h>
#include <cuda_bf16.h>

typedef unsigned long long ull;

#define NC 173
#define NL 400
#define NB 64
#define BPB 8                   // batches per tower block
#define FEAT_PER_C 320          // 32 ch * 10 pool
#define NFEAT (NC * FEAT_PER_C) // 55360
#define KSPLIT 160
#define KCH (NFEAT / KSPLIT)    // 346

#define Y1S 416                 // y1 row stride (left halo 7, right pad)
#define XSS 416                 // xs row stride

__device__ float  g_feat[NB * NFEAT];          // pooled features [b][55360]
__device__ float  g_part[KSPLIT * NB * 128];   // FC1 partials [ks][b][j]
__device__ float  g_w1f[NC * 144];             // BN1-folded conv1 weights
__device__ float  g_t1 [NC * 16];              // BN1-folded bias
__device__ __align__(16) float2 g_w2i[NC * 1792]; // BN2-folded interleaved conv2 weights
__device__ float2 g_t2 [NC * 16];              // BN2-folded bias pairs

// ---------- packed f32x2 helpers (sm_103a FFMA2) ----------
__device__ __forceinline__ ull fma2(ull a, ull b, ull c) {
    ull d;
    asm("fma.rn.f32x2 %0, %1, %2, %3;" : "=l"(d) : "l"(a), "l"(b), "l"(c));
    return d;
}
__device__ __forceinline__ ull add2(ull a, ull b) {
    ull d;
    asm("add.rn.f32x2 %0, %1, %2;" : "=l"(d) : "l"(a), "l"(b));
    return d;
}
__device__ __forceinline__ ull pack2(float lo, float hi) {
    ull d;
    asm("mov.b64 %0, {%1, %2};" : "=l"(d) : "f"(lo), "f"(hi));
    return d;
}
__device__ __forceinline__ float2 unpack2(ull v) {
    float2 r;
    asm("mov.b64 {%0, %1}, %2;" : "=f"(r.x), "=f"(r.y) : "l"(v));
    return r;
}

// =====================================================================
// Kernel P: per-channel weight prep (BN fold + conv2 pair interleave)
// =====================================================================
__global__ __launch_bounds__(256) void prep_kernel(
    const float* __restrict__ w1g, const float* __restrict__ b1,
    const float* __restrict__ g1,  const float* __restrict__ beta1,
    const float* __restrict__ m1,  const float* __restrict__ v1,
    const float* __restrict__ w2g, const float* __restrict__ b2,
    const float* __restrict__ g2,  const float* __restrict__ beta2,
    const float* __restrict__ m2,  const float* __restrict__ v2)
{
    __shared__ float s1s[16], s2s[32], t2s[32];
    const int c = blockIdx.x, tid = threadIdx.x;

    if (tid < 16) {
        int cf = c * 16 + tid;
        float s = g1[cf] * rsqrtf(v1[cf] + 1e-5f);
        s1s[tid] = s;
        g_t1[cf] = s * (b1[cf] - m1[cf]) + beta1[cf];
    }
    if (tid >= 32 && tid < 64) {
        int o = tid - 32, co = c * 32 + o;
        float s = g2[co] * rsqrtf(v2[co] + 1e-5f);
        s2s[o] = s;
        t2s[o] = s * (b2[co] - m2[co]) + beta2[co];
    }
    __syncthreads();

    if (tid < 144)
        g_w1f[c * 144 + tid] = w1g[c * 144 + tid] * s1s[tid / 9];
    if (tid >= 144 && tid < 160) {
        int pr = tid - 144;
        g_t2[c * 16 + pr] = make_float2(t2s[2 * pr], t2s[2 * pr + 1]);
    }
    // interleave: g_w2i[c][(i*7+k)*16 + pr] = {s*w2[o=2pr], s*w2[o=2pr+1]}
    const float* wc = w2g + c * 3584;     // [o][i][k], o-stride 112
    for (int idx = tid; idx < 1792; idx += 256) {
        int pr = idx & 15, ik = idx >> 4;
        int i = ik / 7, k = ik - i * 7;
        int o0 = 2 * pr;
        g_w2i[c * 1792 + idx] = make_float2(wc[o0 * 112 + i * 7 + k] * s2s[o0],
                                            wc[(o0 + 1) * 112 + i * 7 + k] * s2s[o0 + 1]);
    }
}

// =====================================================================
// Kernel A: one block per (c, 8 batches), 320 threads.
// Stage weights once; loop 8 batches: conv1 -> conv2 (FFMA2) -> pool.
// =====================================================================
__global__ __launch_bounds__(320, 2) void tower_kernel(const float* __restrict__ x)
{
    __shared__ __align__(16) float xs[BPB * XSS];     // 8 x rows, pad-4 halo
    __shared__ float w1s[144];                        // folded 16x9
    __shared__ float t1s[16];
    __shared__ __align__(16) float y1s[16 * Y1S];     // conv1 out, halo-7 left
    __shared__ __align__(16) float2 w2p[16 * 7 * 16]; // [i][k][opair]
    __shared__ float2 t2p[16];
    __shared__ __align__(16) float4 pool_p[FEAT_PER_C]; // [ch*10+pw] x 4 subs

    const int blk = blockIdx.x;
    const int bg = blk / NC, c = blk - bg * NC;
    const int b0 = bg * BPB;
    const int tid = threadIdx.x;

    // ---------------- phase 0: stage once per block ----------------
    for (int idx = tid; idx < BPB * 408; idx += 320) {
        int r = idx / 408, j = idx - r * 408;
        xs[r * XSS + j] = (j >= 4 && j < 404)
                        ? x[((b0 + r) * NC + c) * NL + (j - 4)] : 0.f;
    }
    if (tid < 144) w1s[tid] = g_w1f[c * 144 + tid];
    if (tid >= 144 && tid < 160) t1s[tid - 144] = g_t1[c * 16 + tid - 144];
    if (tid >= 160 && tid < 176) t2p[tid - 160] = g_t2[c * 16 + tid - 160];
    {   // w2p copy: 1792 float2 = 896 float4
        const float4* src = reinterpret_cast<const float4*>(g_w2i + c * 1792);
        float4* dst = reinterpret_cast<float4*>(w2p);
        for (int idx = tid; idx < 896; idx += 320) dst[idx] = src[idx];
    }
    if (tid < 256) {     // zero y1 halos once: cols 0..6 and 407..415 (16/row)
        int i = tid >> 4, jj = tid & 15;
        y1s[i * Y1S + (jj < 7 ? jj : 400 + jj)] = 0.f;
    }
    __syncthreads();

    // ---------------- conv1 for batch 0 ----------------
    {
        const float* xb = &xs[0];
        for (int idx = tid; idx < 6400; idx += 320) {
            int f = idx / 400, t = idx - f * 400;
            const float* wf = &w1s[f * 9];
            float a = 0.f;
#pragma unroll
            for (int k = 0; k < 9; ++k) a = fmaf(wf[k], xb[t + k], a);
            y1s[f * Y1S + 7 + t] = fmaxf(a + t1s[f], 0.f);
        }
    }
    __syncthreads();

#pragma unroll 1
    for (int bb = 0; bb < BPB; ++bb) {
        // ---- conv2 (32 x 400) FFMA2 + bias + ReLU + pool partials ----
        {
            const int g  = tid >> 3;       // 0..39: position tile of 10
            const int cg = tid & 7;        // pairs {2cg,2cg+1} -> ch 4cg..4cg+3
            const int t0 = g * 10;

            ull acc[2][10];
#pragma unroll
            for (int p = 0; p < 2; ++p)
#pragma unroll
                for (int t = 0; t < 10; ++t) acc[p][t] = 0ull;

            const ulonglong2* w2u2 = reinterpret_cast<const ulonglong2*>(w2p);

#pragma unroll 1
            for (int i = 0; i < 16; ++i) {
                const float2* ybase =
                    reinterpret_cast<const float2*>(&y1s[i * Y1S + t0 + 4]);
                ull yp[16];
#pragma unroll
                for (int m = 0; m < 8; ++m) {
                    float2 a = ybase[m];
                    yp[2 * m]     = pack2(a.x, a.x);
                    yp[2 * m + 1] = pack2(a.y, a.y);
                }
                const ulonglong2* wr = w2u2 + i * 56 + cg;   // stride 8 per k
#pragma unroll
                for (int k = 0; k < 7; ++k) {
                    ulonglong2 w = wr[k * 8];
#pragma unroll
                    for (int t = 0; t < 10; ++t) {
                        acc[0][t] = fma2(w.x, yp[t + k], acc[0][t]);
                        acc[1][t] = fma2(w.y, yp[t + k], acc[1][t]);
                    }
                }
            }

            // epilogue: +bias, ReLU, pool 10 positions, scatter partial
            const ull* t2u = reinterpret_cast<const ull*>(t2p);
            const int pw = g >> 2;
            const int sub = g & 3;
            float* poolf = reinterpret_cast<float*>(pool_p);
#pragma unroll
            for (int p = 0; p < 2; ++p) {
                int pr = 2 * cg + p;
                ull bi = t2u[pr];
                float mlo = 0.f, mhi = 0.f;
#pragma unroll
                for (int t = 0; t < 10; ++t) {
                    float2 v = unpack2(add2(acc[p][t], bi));
                    mlo = fmaxf(mlo, v.x);
                    mhi = fmaxf(mhi, v.y);
                }
                poolf[((2 * pr) * 10 + pw) * 4 + sub]     = mlo;
                poolf[((2 * pr + 1) * 10 + pw) * 4 + sub] = mhi;
            }
        }
        __syncthreads();

        // ---- writeback(bb) + conv1(bb+1) between the same pair of syncs ----
        {
            float4 v = pool_p[tid];               // FEAT_PER_C == blockDim == 320
            g_feat[(b0 + bb) * NFEAT + c * FEAT_PER_C + tid] =
                fmaxf(fmaxf(v.x, v.y), fmaxf(v.z, v.w));
        }
        if (bb + 1 < BPB) {
            const float* xb = &xs[(bb + 1) * XSS];
            for (int idx = tid; idx < 6400; idx += 320) {
                int f = idx / 400, t = idx - f * 400;
                const float* wf = &w1s[f * 9];
                float a = 0.f;
#pragma unroll
                for (int k = 0; k < 9; ++k) a = fmaf(wf[k], xb[t + k], a);
                y1s[f * Y1S + 7 + t] = fmaxf(a + t1s[f], 0.f);
            }
            __syncthreads();
        }
    }
}

// =====================================================================
// Kernel B: FC1 outer-product, FFMA2, K-split partials
// grid (2 j-tiles of 64, KSPLIT), 256 threads; thread = 4b x 4j
// =====================================================================
__global__ __launch_bounds__(256) void fc1_kernel(const float* __restrict__ wc1)
{
    __shared__ __align__(16) float fs[64 * 66];
    __shared__ __align__(16) float ws[64 * 66];

    const int jt = blockIdx.x, ks = blockIdx.y;
    const int tid = threadIdx.x;
    const int bq = tid >> 4;        // 0..15 -> b rows {bq, bq+16, bq+32, bq+48}
    const int jq = tid & 15;        // 0..15 -> j rows {jq, jq+16, jq+32, jq+48}
    const int kbeg = ks * KCH, kend = kbeg + KCH;

    ull acc[4][4];
#pragma unroll
    for (int rb = 0; rb < 4; ++rb)
#pragma unroll
        for (int rj = 0; rj < 4; ++rj) acc[rb][rj] = 0ull;

    for (int k0 = kbeg; k0 < kend; k0 += 64) {
#pragma unroll
        for (int l = 0; l < 16; ++l) {
            int idx = tid + l * 256;
            int r = idx >> 6, cc = idx & 63;
            int k = k0 + cc;
            fs[r * 66 + cc] = (k < kend) ? g_feat[r * NFEAT + k] : 0.f;
            ws[r * 66 + cc] = (k < kend) ? wc1[(jt * 64 + r) * NFEAT + k] : 0.f;
        }
        __syncthreads();

        const ull* fs2 = reinterpret_cast<const ull*>(fs);
        const ull* ws2 = reinterpret_cast<const ull*>(ws);
#pragma unroll 4
        for (int cc2 = 0; cc2 < 32; ++cc2) {
            ull fv[4], wv[4];
#pragma unroll
            for (int r = 0; r < 4; ++r) fv[r] = fs2[(bq + 16 * r) * 33 + cc2];
#pragma unroll
            for (int r = 0; r < 4; ++r) wv[r] = ws2[(jq + 16 * r) * 33 + cc2];
#pragma unroll
            for (int rb = 0; rb < 4; ++rb)
#pragma unroll
                for (int rj = 0; rj < 4; ++rj)
                    acc[rb][rj] = fma2(fv[rb], wv[rj], acc[rb][rj]);
        }
        __syncthreads();
    }

#pragma unroll
    for (int rb = 0; rb < 4; ++rb) {
        int b = bq + 16 * rb;
#pragma unroll
        for (int rj = 0; rj < 4; ++rj) {
            int j = jt * 64 + jq + 16 * rj;
            float2 v = unpack2(acc[rb][rj]);
            g_part[(ks * NB + b) * 128 + j] = v.x + v.y;
        }
    }
}

// =====================================================================
// Kernel C: reduce partials (8-way split), bias1, ReLU, FC2
// =====================================================================
__global__ __launch_bounds__(1024) void fc2_kernel(
    const float* __restrict__ bc1, const float* __restrict__ wc2,
    const float* __restrict__ bc2, float* __restrict__ out)
{
    __shared__ float part[8][128];
    __shared__ float red[4];
    const int b = blockIdx.x;
    const int j = threadIdx.x & 127, r = threadIdx.x >> 7;   // r 0..7

    float s = 0.f;
#pragma unroll 5
    for (int ks = r; ks < KSPLIT; ks += 8)
        s += g_part[(ks * NB + b) * 128 + j];
    part[r][j] = s;
    __syncthreads();

    if (threadIdx.x < 128) {
        float t = bc1[j];
#pragma unroll
        for (int r2 = 0; r2 < 8; ++r2) t += part[r2][j];
        float v = fmaxf(t, 0.f) * wc2[j];
#pragma unroll
        for (int o = 16; o > 0; o >>= 1)
            v += __shfl_down_sync(0xffffffffu, v, o);
        if ((j & 31) == 0) red[j >> 5] = v;
    }
    __syncthreads();
    if (threadIdx.x == 0) out[b] = red[0] + red[1] + red[2] + red[3] + bc2[0];
}

// =====================================================================
extern "C" void kernel_launch(void* const* d_in, const int* in_sizes, int n_in,
                              void* d_out, int out_size)
{
    const float* x     = (const float*)d_in[0];
    const float* w1    = (const float*)d_in[1];
    const float* b1    = (const float*)d_in[2];
    const float* g1    = (const float*)d_in[3];
    const float* beta1 = (const float*)d_in[4];
    const float* m1    = (const float*)d_in[5];
    const float* v1    = (const float*)d_in[6];
    const float* w2    = (const float*)d_in[7];
    const float* b2    = (const float*)d_in[8];
    const float* g2    = (const float*)d_in[9];
    const float* beta2 = (const float*)d_in[10];
    const float* m2    = (const float*)d_in[11];
    const float* v2    = (const float*)d_in[12];
    const float* wc1   = (const float*)d_in[13];
    const float* bc1   = (const float*)d_in[14];
    const float* wc2   = (const float*)d_in[15];
    const float* bc2   = (const float*)d_in[16];
    float* out = (float*)d_out;

    prep_kernel<<<NC, 256>>>(w1, b1, g1, beta1, m1, v1,
                             w2, b2, g2, beta2, m2, v2);
    tower_kernel<<<NC * (NB / BPB), 320>>>(x);
    fc1_kernel<<<dim3(2, KSPLIT), 256>>>(wc1);
    fc2_kernel<<<NB, 1024>>>(bc1, wc2, bc2, out);
}

// round 15
// speedup vs baseline: 1.4516x; 1.1254x over previous
#include <cuda_runtime.h>
#include <cuda_bf16.h>

typedef unsigned long long ull;

#define NC 173
#define NL 400
#define NB 64
#define BPB 4                   // batches per tower block (4 was optimal)
#define FEAT_PER_C 320          // 32 ch * 10 pool
#define NFEAT (NC * FEAT_PER_C) // 55360
#define KSPLIT 160
#define KCH (NFEAT / KSPLIT)    // 346

#define Y1S 416                 // y1 row stride (left halo 7, right pad)
#define XSS 416                 // xs row stride

__device__ float  g_feat[NB * NFEAT];          // pooled features [b][55360]
__device__ float  g_part[KSPLIT * NB * 128];   // FC1 partials [ks][b][j]
__device__ float  g_w1f[NC * 144];             // BN1-folded conv1 weights
__device__ float  g_t1 [NC * 16];              // BN1-folded bias
__device__ __align__(16) float2 g_w2i[NC * 1792]; // BN2-folded interleaved conv2 weights
__device__ float2 g_t2 [NC * 16];              // BN2-folded bias pairs

// ---------- packed f32x2 helpers (sm_103a FFMA2) ----------
__device__ __forceinline__ ull fma2(ull a, ull b, ull c) {
    ull d;
    asm("fma.rn.f32x2 %0, %1, %2, %3;" : "=l"(d) : "l"(a), "l"(b), "l"(c));
    return d;
}
__device__ __forceinline__ ull add2(ull a, ull b) {
    ull d;
    asm("add.rn.f32x2 %0, %1, %2;" : "=l"(d) : "l"(a), "l"(b));
    return d;
}
__device__ __forceinline__ ull pack2(float lo, float hi) {
    ull d;
    asm("mov.b64 %0, {%1, %2};" : "=l"(d) : "f"(lo), "f"(hi));
    return d;
}
__device__ __forceinline__ float2 unpack2(ull v) {
    float2 r;
    asm("mov.b64 {%0, %1}, %2;" : "=f"(r.x), "=f"(r.y) : "l"(v));
    return r;
}

// =====================================================================
// Kernel P: per-channel weight prep (BN fold + conv2 pair interleave)
// =====================================================================
__global__ __launch_bounds__(256) void prep_kernel(
    const float* __restrict__ w1g, const float* __restrict__ b1,
    const float* __restrict__ g1,  const float* __restrict__ beta1,
    const float* __restrict__ m1,  const float* __restrict__ v1,
    const float* __restrict__ w2g, const float* __restrict__ b2,
    const float* __restrict__ g2,  const float* __restrict__ beta2,
    const float* __restrict__ m2,  const float* __restrict__ v2)
{
    __shared__ float s1s[16], s2s[32], t2s[32];
    const int c = blockIdx.x, tid = threadIdx.x;

    if (tid < 16) {
        int cf = c * 16 + tid;
        float s = g1[cf] * rsqrtf(v1[cf] + 1e-5f);
        s1s[tid] = s;
        g_t1[cf] = s * (b1[cf] - m1[cf]) + beta1[cf];
    }
    if (tid >= 32 && tid < 64) {
        int o = tid - 32, co = c * 32 + o;
        float s = g2[co] * rsqrtf(v2[co] + 1e-5f);
        s2s[o] = s;
        t2s[o] = s * (b2[co] - m2[co]) + beta2[co];
    }
    __syncthreads();

    if (tid < 144)
        g_w1f[c * 144 + tid] = w1g[c * 144 + tid] * s1s[tid / 9];
    if (tid >= 144 && tid < 160) {
        int pr = tid - 144;
        g_t2[c * 16 + pr] = make_float2(t2s[2 * pr], t2s[2 * pr + 1]);
    }
    // interleave: g_w2i[c][(i*7+k)*16 + pr] = {s*w2[o=2pr], s*w2[o=2pr+1]}
    const float* wc = w2g + c * 3584;     // [o][i][k], o-stride 112
    for (int idx = tid; idx < 1792; idx += 256) {
        int pr = idx & 15, ik = idx >> 4;
        int i = ik / 7, k = ik - i * 7;
        int o0 = 2 * pr;
        g_w2i[c * 1792 + idx] = make_float2(wc[o0 * 112 + i * 7 + k] * s2s[o0],
                                            wc[(o0 + 1) * 112 + i * 7 + k] * s2s[o0 + 1]);
    }
}

// =====================================================================
// conv1 (chunked register window): thread = (f = tid&15, tile = tid>>4).
// 9 weights in regs; 5 chunks x {3 LDS.128, 36 FFMA, 4 STS}.
// =====================================================================
__device__ __forceinline__ void conv1_chunked(
    const float* __restrict__ xb,      // xs row (pad-4 halo), 16B aligned
    const float* __restrict__ w1s,     // 16 x 9 folded weights
    const float* __restrict__ t1s,     // 16 folded biases
    float* __restrict__ y1s, int tid)
{
    const int f = tid & 15;
    const int t0 = (tid >> 4) * 20;    // 0,20,...,380

    const float* wf = &w1s[f * 9];
    const float w0 = wf[0], w1 = wf[1], w2 = wf[2], w3 = wf[3], w4 = wf[4],
                w5 = wf[5], w6 = wf[6], w7 = wf[7], w8 = wf[8];
    const float bias = t1s[f];

    const float4* xb4 = reinterpret_cast<const float4*>(xb + t0);  // 80B -> 16B ok
    float* ydst = &y1s[f * Y1S + 7 + t0];

#pragma unroll 1
    for (int j = 0; j < 5; ++j) {
        float4 A = xb4[j], B = xb4[j + 1], C = xb4[j + 2];
        float win[12] = {A.x, A.y, A.z, A.w, B.x, B.y, B.z, B.w,
                         C.x, C.y, C.z, C.w};
#pragma unroll
        for (int t = 0; t < 4; ++t) {
            float a;
            a = w0 * win[t];
            a = fmaf(w1, win[t + 1], a);
            a = fmaf(w2, win[t + 2], a);
            a = fmaf(w3, win[t + 3], a);
            a = fmaf(w4, win[t + 4], a);
            a = fmaf(w5, win[t + 5], a);
            a = fmaf(w6, win[t + 6], a);
            a = fmaf(w7, win[t + 7], a);
            a = fmaf(w8, win[t + 8], a);
            ydst[4 * j + t] = fmaxf(a + bias, 0.f);
        }
    }
}

// =====================================================================
// Kernel A: one block per (c, 4 batches), 320 threads.
// Stage weights once; loop 4 batches: conv1 -> conv2 (FFMA2) -> pool.
// =====================================================================
__global__ __launch_bounds__(320, 2) void tower_kernel(const float* __restrict__ x)
{
    __shared__ __align__(16) float xs[BPB * XSS];     // 4 x rows, pad-4 halo
    __shared__ float w1s[144];                        // folded 16x9
    __shared__ float t1s[16];
    __shared__ __align__(16) float y1s[16 * Y1S];     // conv1 out, halo-7 left
    __shared__ __align__(16) float2 w2p[16 * 7 * 16]; // [i][k][opair]
    __shared__ float2 t2p[16];
    __shared__ __align__(16) float4 pool_p[FEAT_PER_C]; // [ch*10+pw] x 4 subs

    const int blk = blockIdx.x;
    const int bg = blk / NC, c = blk - bg * NC;
    const int b0 = bg * BPB;
    const int tid = threadIdx.x;

    // ---------------- phase 0: stage once per block ----------------
    for (int idx = tid; idx < BPB * 408; idx += 320) {
        int r = idx / 408, j = idx - r * 408;
        xs[r * XSS + j] = (j >= 4 && j < 404)
                        ? x[((b0 + r) * NC + c) * NL + (j - 4)] : 0.f;
    }
    if (tid < 144) w1s[tid] = g_w1f[c * 144 + tid];
    if (tid >= 144 && tid < 160) t1s[tid - 144] = g_t1[c * 16 + tid - 144];
    if (tid >= 160 && tid < 176) t2p[tid - 160] = g_t2[c * 16 + tid - 160];
    {   // w2p copy: 1792 float2 = 896 float4
        const float4* src = reinterpret_cast<const float4*>(g_w2i + c * 1792);
        float4* dst = reinterpret_cast<float4*>(w2p);
        for (int idx = tid; idx < 896; idx += 320) dst[idx] = src[idx];
    }
    if (tid < 256) {     // zero y1 halos once: cols 0..6 and 407..415 (16/row)
        int i = tid >> 4, jj = tid & 15;
        y1s[i * Y1S + (jj < 7 ? jj : 400 + jj)] = 0.f;
    }
    __syncthreads();

    // ---------------- conv1 for batch 0 ----------------
    conv1_chunked(&xs[0], w1s, t1s, y1s, tid);
    __syncthreads();

#pragma unroll 1
    for (int bb = 0; bb < BPB; ++bb) {
        // ---- conv2 (32 x 400) FFMA2 + bias + ReLU + pool partials ----
        {
            const int g  = tid >> 3;       // 0..39: position tile of 10
            const int cg = tid & 7;        // pairs {2cg,2cg+1} -> ch 4cg..4cg+3
            const int t0 = g * 10;

            ull acc[2][10];
#pragma unroll
            for (int p = 0; p < 2; ++p)
#pragma unroll
                for (int t = 0; t < 10; ++t) acc[p][t] = 0ull;

            const ulonglong2* w2u2 = reinterpret_cast<const ulonglong2*>(w2p);

#pragma unroll 1
            for (int i = 0; i < 16; ++i) {
                const float2* ybase =
                    reinterpret_cast<const float2*>(&y1s[i * Y1S + t0 + 4]);
                ull yp[16];
#pragma unroll
                for (int m = 0; m < 8; ++m) {
                    float2 a = ybase[m];
                    yp[2 * m]     = pack2(a.x, a.x);
                    yp[2 * m + 1] = pack2(a.y, a.y);
                }
                const ulonglong2* wr = w2u2 + i * 56 + cg;   // stride 8 per k
#pragma unroll
                for (int k = 0; k < 7; ++k) {
                    ulonglong2 w = wr[k * 8];
#pragma unroll
                    for (int t = 0; t < 10; ++t) {
                        acc[0][t] = fma2(w.x, yp[t + k], acc[0][t]);
                        acc[1][t] = fma2(w.y, yp[t + k], acc[1][t]);
                    }
                }
            }

            // epilogue: +bias, ReLU, pool 10 positions, scatter partial
            const ull* t2u = reinterpret_cast<const ull*>(t2p);
            const int pw = g >> 2;
            const int sub = g & 3;
            float* poolf = reinterpret_cast<float*>(pool_p);
#pragma unroll
            for (int p = 0; p < 2; ++p) {
                int pr = 2 * cg + p;
                ull bi = t2u[pr];
                float mlo = 0.f, mhi = 0.f;
#pragma unroll
                for (int t = 0; t < 10; ++t) {
                    float2 v = unpack2(add2(acc[p][t], bi));
                    mlo = fmaxf(mlo, v.x);
                    mhi = fmaxf(mhi, v.y);
                }
                poolf[((2 * pr) * 10 + pw) * 4 + sub]     = mlo;
                poolf[((2 * pr + 1) * 10 + pw) * 4 + sub] = mhi;
            }
        }
        __syncthreads();

        // ---- writeback(bb) + conv1(bb+1) between the same pair of syncs ----
        {
            float4 v = pool_p[tid];               // FEAT_PER_C == blockDim == 320
            g_feat[(b0 + bb) * NFEAT + c * FEAT_PER_C + tid] =
                fmaxf(fmaxf(v.x, v.y), fmaxf(v.z, v.w));
        }
        if (bb + 1 < BPB) {
            conv1_chunked(&xs[(bb + 1) * XSS], w1s, t1s, y1s, tid);
            __syncthreads();
        }
    }
}

// =====================================================================
// Kernel B: FC1 outer-product, FFMA2, K-split partials
// grid (2 j-tiles of 64, KSPLIT), 256 threads; thread = 4b x 4j
// =====================================================================
__global__ __launch_bounds__(256) void fc1_kernel(const float* __restrict__ wc1)
{
    __shared__ __align__(16) float fs[64 * 66];
    __shared__ __align__(16) float ws[64 * 66];

    const int jt = blockIdx.x, ks = blockIdx.y;
    const int tid = threadIdx.x;
    const int bq = tid >> 4;        // 0..15 -> b rows {bq, bq+16, bq+32, bq+48}
    const int jq = tid & 15;        // 0..15 -> j rows {jq, jq+16, jq+32, jq+48}
    const int kbeg = ks * KCH, kend = kbeg + KCH;

    ull acc[4][4];
#pragma unroll
    for (int rb = 0; rb < 4; ++rb)
#pragma unroll
        for (int rj = 0; rj < 4; ++rj) acc[rb][rj] = 0ull;

    for (int k0 = kbeg; k0 < kend; k0 += 64) {
#pragma unroll
        for (int l = 0; l < 16; ++l) {
            int idx = tid + l * 256;
            int r = idx >> 6, cc = idx & 63;
            int k = k0 + cc;
            fs[r * 66 + cc] = (k < kend) ? g_feat[r * NFEAT + k] : 0.f;
            ws[r * 66 + cc] = (k < kend) ? wc1[(jt * 64 + r) * NFEAT + k] : 0.f;
        }
        __syncthreads();

        const ull* fs2 = reinterpret_cast<const ull*>(fs);
        const ull* ws2 = reinterpret_cast<const ull*>(ws);
#pragma unroll 4
        for (int cc2 = 0; cc2 < 32; ++cc2) {
            ull fv[4], wv[4];
#pragma unroll
            for (int r = 0; r < 4; ++r) fv[r] = fs2[(bq + 16 * r) * 33 + cc2];
#pragma unroll
            for (int r = 0; r < 4; ++r) wv[r] = ws2[(jq + 16 * r) * 33 + cc2];
#pragma unroll
            for (int rb = 0; rb < 4; ++rb)
#pragma unroll
                for (int rj = 0; rj < 4; ++rj)
                    acc[rb][rj] = fma2(fv[rb], wv[rj], acc[rb][rj]);
        }
        __syncthreads();
    }

#pragma unroll
    for (int rb = 0; rb < 4; ++rb) {
        int b = bq + 16 * rb;
#pragma unroll
        for (int rj = 0; rj < 4; ++rj) {
            int j = jt * 64 + jq + 16 * rj;
            float2 v = unpack2(acc[rb][rj]);
            g_part[(ks * NB + b) * 128 + j] = v.x + v.y;
        }
    }
}

// =====================================================================
// Kernel C: reduce partials (8-way split), bias1, ReLU, FC2
// =====================================================================
__global__ __launch_bounds__(1024) void fc2_kernel(
    const float* __restrict__ bc1, const float* __restrict__ wc2,
    const float* __restrict__ bc2, float* __restrict__ out)
{
    __shared__ float part[8][128];
    __shared__ float red[4];
    const int b = blockIdx.x;
    const int j = threadIdx.x & 127, r = threadIdx.x >> 7;   // r 0..7

    float s = 0.f;
#pragma unroll 5
    for (int ks = r; ks < KSPLIT; ks += 8)
        s += g_part[(ks * NB + b) * 128 + j];
    part[r][j] = s;
    __syncthreads();

    if (threadIdx.x < 128) {
        float t = bc1[j];
#pragma unroll
        for (int r2 = 0; r2 < 8; ++r2) t += part[r2][j];
        float v = fmaxf(t, 0.f) * wc2[j];
#pragma unroll
        for (int o = 16; o > 0; o >>= 1)
            v += __shfl_down_sync(0xffffffffu, v, o);
        if ((j & 31) == 0) red[j >> 5] = v;
    }
    __syncthreads();
    if (threadIdx.x == 0) out[b] = red[0] + red[1] + red[2] + red[3] + bc2[0];
}

// =====================================================================
extern "C" void kernel_launch(void* const* d_in, const int* in_sizes, int n_in,
                              void* d_out, int out_size)
{
    const float* x     = (const float*)d_in[0];
    const float* w1    = (const float*)d_in[1];
    const float* b1    = (const float*)d_in[2];
    const float* g1    = (const float*)d_in[3];
    const float* beta1 = (const float*)d_in[4];
    const float* m1    = (const float*)d_in[5];
    const float* v1    = (const float*)d_in[6];
    const float* w2    = (const float*)d_in[7];
    const float* b2    = (const float*)d_in[8];
    const float* g2    = (const float*)d_in[9];
    const float* beta2 = (const float*)d_in[10];
    const float* m2    = (const float*)d_in[11];
    const float* v2    = (const float*)d_in[12];
    const float* wc1   = (const float*)d_in[13];
    const float* bc1   = (const float*)d_in[14];
    const float* wc2   = (const float*)d_in[15];
    const float* bc2   = (const float*)d_in[16];
    float* out = (float*)d_out;

    prep_kernel<<<NC, 256>>>(w1, b1, g1, beta1, m1, v1,
                             w2, b2, g2, beta2, m2, v2);
    tower_kernel<<<NC * (NB / BPB), 320>>>(x);
    fc1_kernel<<<dim3(2, KSPLIT), 256>>>(wc1);
    fc2_kernel<<<NB, 1024>>>(bc1, wc2, bc2, out);
}

// round 16
// speedup vs baseline: 1.5513x; 1.0687x over previous
#include <cuda_runtime.h>
#include <cuda_bf16.h>

typedef unsigned long long ull;

#define NC 173
#define NL 400
#define NB 64
#define BPB 4                   // batches per tower block
#define FEAT_PER_C 320          // 32 ch * 10 pool
#define NFEAT (NC * FEAT_PER_C) // 55360
#define KSPLIT 160
#define KCH (NFEAT / KSPLIT)    // 346

#define Y1S 416                 // y1 row stride (left halo 7, right pad)
#define Y1BUF (16 * Y1S)        // one y1 buffer (floats)
#define XSS 416                 // xs row stride

__device__ float  g_feat[NB * NFEAT];          // pooled features [b][55360]
__device__ float  g_part[KSPLIT * NB * 128];   // FC1 partials [ks][b][j]
__device__ float  g_w1f[NC * 144];             // BN1-folded conv1 weights
__device__ float  g_t1 [NC * 16];              // BN1-folded bias
__device__ __align__(16) float2 g_w2i[NC * 1792]; // BN2-folded interleaved conv2 weights
__device__ float2 g_t2 [NC * 16];              // BN2-folded bias pairs

// ---------- packed f32x2 helpers (sm_103a FFMA2) ----------
__device__ __forceinline__ ull fma2(ull a, ull b, ull c) {
    ull d;
    asm("fma.rn.f32x2 %0, %1, %2, %3;" : "=l"(d) : "l"(a), "l"(b), "l"(c));
    return d;
}
__device__ __forceinline__ ull add2(ull a, ull b) {
    ull d;
    asm("add.rn.f32x2 %0, %1, %2;" : "=l"(d) : "l"(a), "l"(b));
    return d;
}
__device__ __forceinline__ ull pack2(float lo, float hi) {
    ull d;
    asm("mov.b64 %0, {%1, %2};" : "=l"(d) : "f"(lo), "f"(hi));
    return d;
}
__device__ __forceinline__ float2 unpack2(ull v) {
    float2 r;
    asm("mov.b64 {%0, %1}, %2;" : "=f"(r.x), "=f"(r.y) : "l"(v));
    return r;
}

// =====================================================================
// Kernel P: per-channel weight prep (BN fold + conv2 pair interleave)
// =====================================================================
__global__ __launch_bounds__(256) void prep_kernel(
    const float* __restrict__ w1g, const float* __restrict__ b1,
    const float* __restrict__ g1,  const float* __restrict__ beta1,
    const float* __restrict__ m1,  const float* __restrict__ v1,
    const float* __restrict__ w2g, const float* __restrict__ b2,
    const float* __restrict__ g2,  const float* __restrict__ beta2,
    const float* __restrict__ m2,  const float* __restrict__ v2)
{
    __shared__ float s1s[16], s2s[32], t2s[32];
    const int c = blockIdx.x, tid = threadIdx.x;

    if (tid < 16) {
        int cf = c * 16 + tid;
        float s = g1[cf] * rsqrtf(v1[cf] + 1e-5f);
        s1s[tid] = s;
        g_t1[cf] = s * (b1[cf] - m1[cf]) + beta1[cf];
    }
    if (tid >= 32 && tid < 64) {
        int o = tid - 32, co = c * 32 + o;
        float s = g2[co] * rsqrtf(v2[co] + 1e-5f);
        s2s[o] = s;
        t2s[o] = s * (b2[co] - m2[co]) + beta2[co];
    }
    __syncthreads();

    if (tid < 144)
        g_w1f[c * 144 + tid] = w1g[c * 144 + tid] * s1s[tid / 9];
    if (tid >= 144 && tid < 160) {
        int pr = tid - 144;
        g_t2[c * 16 + pr] = make_float2(t2s[2 * pr], t2s[2 * pr + 1]);
    }
    // interleave: g_w2i[c][(i*7+k)*16 + pr] = {s*w2[o=2pr], s*w2[o=2pr+1]}
    const float* wc = w2g + c * 3584;     // [o][i][k], o-stride 112
    for (int idx = tid; idx < 1792; idx += 256) {
        int pr = idx & 15, ik = idx >> 4;
        int i = ik / 7, k = ik - i * 7;
        int o0 = 2 * pr;
        g_w2i[c * 1792 + idx] = make_float2(wc[o0 * 112 + i * 7 + k] * s2s[o0],
                                            wc[(o0 + 1) * 112 + i * 7 + k] * s2s[o0 + 1]);
    }
}

// =====================================================================
// conv1 (chunked register window): thread = (f = tid&15, tile = tid>>4).
// 9 weights in regs; 5 chunks x {3 LDS.128, 36 FFMA, 4 STS}.
// =====================================================================
__device__ __forceinline__ void conv1_chunked(
    const float* __restrict__ xb,      // xs row (pad-4 halo), 16B aligned
    const float* __restrict__ w1s,     // 16 x 9 folded weights
    const float* __restrict__ t1s,     // 16 folded biases
    float* __restrict__ ybuf, int tid)
{
    const int f = tid & 15;
    const int t0 = (tid >> 4) * 20;    // 0,20,...,380

    const float* wf = &w1s[f * 9];
    const float w0 = wf[0], w1 = wf[1], w2 = wf[2], w3 = wf[3], w4 = wf[4],
                w5 = wf[5], w6 = wf[6], w7 = wf[7], w8 = wf[8];
    const float bias = t1s[f];

    const float4* xb4 = reinterpret_cast<const float4*>(xb + t0);  // 80B -> 16B ok
    float* ydst = &ybuf[f * Y1S + 7 + t0];

#pragma unroll 1
    for (int j = 0; j < 5; ++j) {
        float4 A = xb4[j], B = xb4[j + 1], C = xb4[j + 2];
        float win[12] = {A.x, A.y, A.z, A.w, B.x, B.y, B.z, B.w,
                         C.x, C.y, C.z, C.w};
#pragma unroll
        for (int t = 0; t < 4; ++t) {
            float a;
            a = w0 * win[t];
            a = fmaf(w1, win[t + 1], a);
            a = fmaf(w2, win[t + 2], a);
            a = fmaf(w3, win[t + 3], a);
            a = fmaf(w4, win[t + 4], a);
            a = fmaf(w5, win[t + 5], a);
            a = fmaf(w6, win[t + 6], a);
            a = fmaf(w7, win[t + 7], a);
            a = fmaf(w8, win[t + 8], a);
            ydst[4 * j + t] = fmaxf(a + bias, 0.f);
        }
    }
}

// =====================================================================
// Kernel A: one block per (c, 4 batches), 320 threads.
// Double-buffered y1; one sync per batch; shuffle-reduced pooling.
// =====================================================================
__global__ __launch_bounds__(320, 2) void tower_kernel(const float* __restrict__ x)
{
    __shared__ __align__(16) float xs[BPB * XSS];     // 4 x rows, pad-4 halo
    __shared__ float w1s[144];                        // folded 16x9
    __shared__ float t1s[16];
    __shared__ __align__(16) float y1s[2 * Y1BUF];    // DOUBLE-buffered conv1 out
    __shared__ __align__(16) float2 w2p[16 * 7 * 16]; // [i][k][opair]
    __shared__ float2 t2p[16];

    const int blk = blockIdx.x;
    const int bg = blk / NC, c = blk - bg * NC;
    const int b0 = bg * BPB;
    const int tid = threadIdx.x;

    // ---------------- phase 0: stage once per block ----------------
    for (int idx = tid; idx < BPB * 408; idx += 320) {
        int r = idx / 408, j = idx - r * 408;
        xs[r * XSS + j] = (j >= 4 && j < 404)
                        ? x[((b0 + r) * NC + c) * NL + (j - 4)] : 0.f;
    }
    if (tid < 144) w1s[tid] = g_w1f[c * 144 + tid];
    if (tid >= 144 && tid < 160) t1s[tid - 144] = g_t1[c * 16 + tid - 144];
    if (tid >= 160 && tid < 176) t2p[tid - 160] = g_t2[c * 16 + tid - 160];
    {   // w2p copy: 1792 float2 = 896 float4
        const float4* src = reinterpret_cast<const float4*>(g_w2i + c * 1792);
        float4* dst = reinterpret_cast<float4*>(w2p);
        for (int idx = tid; idx < 896; idx += 320) dst[idx] = src[idx];
    }
    // zero halos of BOTH y1 buffers: cols 0..6 and 407..415, 16 rows, 2 bufs
    for (int idx = tid; idx < 512; idx += 320) {
        int buf = idx >> 8, rem = idx & 255;
        int i = rem >> 4, jj = rem & 15;
        y1s[buf * Y1BUF + i * Y1S + (jj < 7 ? jj : 400 + jj)] = 0.f;
    }
    __syncthreads();

    // ---------------- conv1 for batch 0 -> buffer 0 ----------------
    conv1_chunked(&xs[0], w1s, t1s, &y1s[0], tid);
    __syncthreads();

#pragma unroll 1
    for (int bb = 0; bb < BPB; ++bb) {
        // ---- conv2 (32 x 400) FFMA2 + bias + ReLU + shfl-pool + STG ----
        {
            const int g  = tid >> 3;       // 0..39: position tile of 10
            const int cg = tid & 7;        // pairs {2cg,2cg+1} -> ch 4cg..4cg+3
            const int t0 = g * 10;
            const float* ycur = &y1s[(bb & 1) * Y1BUF];

            ull acc[2][10];
#pragma unroll
            for (int p = 0; p < 2; ++p)
#pragma unroll
                for (int t = 0; t < 10; ++t) acc[p][t] = 0ull;

            const ulonglong2* w2u2 = reinterpret_cast<const ulonglong2*>(w2p);

#pragma unroll 1
            for (int i = 0; i < 16; ++i) {
                const float2* ybase =
                    reinterpret_cast<const float2*>(&ycur[i * Y1S + t0 + 4]);
                ull yp[16];
#pragma unroll
                for (int m = 0; m < 8; ++m) {
                    float2 a = ybase[m];
                    yp[2 * m]     = pack2(a.x, a.x);
                    yp[2 * m + 1] = pack2(a.y, a.y);
                }
                const ulonglong2* wr = w2u2 + i * 56 + cg;   // stride 8 per k
#pragma unroll
                for (int k = 0; k < 7; ++k) {
                    ulonglong2 w = wr[k * 8];
#pragma unroll
                    for (int t = 0; t < 10; ++t) {
                        acc[0][t] = fma2(w.x, yp[t + k], acc[0][t]);
                        acc[1][t] = fma2(w.y, yp[t + k], acc[1][t]);
                    }
                }
            }

            // epilogue: +bias, ReLU, pool 10 local positions, then reduce the
            // 4 sub-tiles of each 40-wide window across lanes (xor 8, 16).
            // warp w == window index; lanes {cg, cg+8, cg+16, cg+24} share it.
            const ull* t2u = reinterpret_cast<const ull*>(t2p);
            float m4[4];
#pragma unroll
            for (int p = 0; p < 2; ++p) {
                int pr = 2 * cg + p;
                ull bi = t2u[pr];
                float mlo = 0.f, mhi = 0.f;
#pragma unroll
                for (int t = 0; t < 10; ++t) {
                    float2 v = unpack2(add2(acc[p][t], bi));
                    mlo = fmaxf(mlo, v.x);
                    mhi = fmaxf(mhi, v.y);
                }
                m4[2 * p]     = mlo;   // channel 4cg + 2p
                m4[2 * p + 1] = mhi;   // channel 4cg + 2p + 1
            }
#pragma unroll
            for (int q = 0; q < 4; ++q) {
                m4[q] = fmaxf(m4[q], __shfl_xor_sync(0xffffffffu, m4[q], 8));
                m4[q] = fmaxf(m4[q], __shfl_xor_sync(0xffffffffu, m4[q], 16));
            }
            const int lane = tid & 31;
            if (lane < 8) {                      // lane == cg, sub == 0
                const int w = tid >> 5;          // pool window 0..9
                float* fb = &g_feat[(b0 + bb) * NFEAT + c * FEAT_PER_C];
#pragma unroll
                for (int q = 0; q < 4; ++q)
                    fb[(4 * cg + q) * 10 + w] = m4[q];
            }
        }

        // ---- conv1(bb+1) into the OTHER buffer (no barrier needed) ----
        if (bb + 1 < BPB)
            conv1_chunked(&xs[(bb + 1) * XSS], w1s, t1s,
                          &y1s[((bb + 1) & 1) * Y1BUF], tid);
        __syncthreads();
    }
}

// =====================================================================
// Kernel B: FC1 outer-product, FFMA2, K-split partials
// grid (2 j-tiles of 64, KSPLIT), 256 threads; thread = 4b x 4j
// =====================================================================
__global__ __launch_bounds__(256) void fc1_kernel(const float* __restrict__ wc1)
{
    __shared__ __align__(16) float fs[64 * 66];
    __shared__ __align__(16) float ws[64 * 66];

    const int jt = blockIdx.x, ks = blockIdx.y;
    const int tid = threadIdx.x;
    const int bq = tid >> 4;        // 0..15 -> b rows {bq, bq+16, bq+32, bq+48}
    const int jq = tid & 15;        // 0..15 -> j rows {jq, jq+16, jq+32, jq+48}
    const int kbeg = ks * KCH, kend = kbeg + KCH;

    ull acc[4][4];
#pragma unroll
    for (int rb = 0; rb < 4; ++rb)
#pragma unroll
        for (int rj = 0; rj < 4; ++rj) acc[rb][rj] = 0ull;

    for (int k0 = kbeg; k0 < kend; k0 += 64) {
#pragma unroll
        for (int l = 0; l < 16; ++l) {
            int idx = tid + l * 256;
            int r = idx >> 6, cc = idx & 63;
            int k = k0 + cc;
            fs[r * 66 + cc] = (k < kend) ? g_feat[r * NFEAT + k] : 0.f;
            ws[r * 66 + cc] = (k < kend) ? wc1[(jt * 64 + r) * NFEAT + k] : 0.f;
        }
        __syncthreads();

        const ull* fs2 = reinterpret_cast<const ull*>(fs);
        const ull* ws2 = reinterpret_cast<const ull*>(ws);
#pragma unroll 4
        for (int cc2 = 0; cc2 < 32; ++cc2) {
            ull fv[4], wv[4];
#pragma unroll
            for (int r = 0; r < 4; ++r) fv[r] = fs2[(bq + 16 * r) * 33 + cc2];
#pragma unroll
            for (int r = 0; r < 4; ++r) wv[r] = ws2[(jq + 16 * r) * 33 + cc2];
#pragma unroll
            for (int rb = 0; rb < 4; ++rb)
#pragma unroll
                for (int rj = 0; rj < 4; ++rj)
                    acc[rb][rj] = fma2(fv[rb], wv[rj], acc[rb][rj]);
        }
        __syncthreads();
    }

#pragma unroll
    for (int rb = 0; rb < 4; ++rb) {
        int b = bq + 16 * rb;
#pragma unroll
        for (int rj = 0; rj < 4; ++rj) {
            int j = jt * 64 + jq + 16 * rj;
            float2 v = unpack2(acc[rb][rj]);
            g_part[(ks * NB + b) * 128 + j] = v.x + v.y;
        }
    }
}

// =====================================================================
// Kernel C: reduce partials (8-way split), bias1, ReLU, FC2
// =====================================================================
__global__ __launch_bounds__(1024) void fc2_kernel(
    const float* __restrict__ bc1, const float* __restrict__ wc2,
    const float* __restrict__ bc2, float* __restrict__ out)
{
    __shared__ float part[8][128];
    __shared__ float red[4];
    const int b = blockIdx.x;
    const int j = threadIdx.x & 127, r = threadIdx.x >> 7;   // r 0..7

    float s = 0.f;
#pragma unroll 5
    for (int ks = r; ks < KSPLIT; ks += 8)
        s += g_part[(ks * NB + b) * 128 + j];
    part[r][j] = s;
    __syncthreads();

    if (threadIdx.x < 128) {
        float t = bc1[j];
#pragma unroll
        for (int r2 = 0; r2 < 8; ++r2) t += part[r2][j];
        float v = fmaxf(t, 0.f) * wc2[j];
#pragma unroll
        for (int o = 16; o > 0; o >>= 1)
            v += __shfl_down_sync(0xffffffffu, v, o);
        if ((j & 31) == 0) red[j >> 5] = v;
    }
    __syncthreads();
    if (threadIdx.x == 0) out[b] = red[0] + red[1] + red[2] + red[3] + bc2[0];
}

// =====================================================================
extern "C" void kernel_launch(void* const* d_in, const int* in_sizes, int n_in,
                              void* d_out, int out_size)
{
    const float* x     = (const float*)d_in[0];
    const float* w1    = (const float*)d_in[1];
    const float* b1    = (const float*)d_in[2];
    const float* g1    = (const float*)d_in[3];
    const float* beta1 = (const float*)d_in[4];
    const float* m1    = (const float*)d_in[5];
    const float* v1    = (const float*)d_in[6];
    const float* w2    = (const float*)d_in[7];
    const float* b2    = (const float*)d_in[8];
    const float* g2    = (const float*)d_in[9];
    const float* beta2 = (const float*)d_in[10];
    const float* m2    = (const float*)d_in[11];
    const float* v2    = (const float*)d_in[12];
    const float* wc1   = (const float*)d_in[13];
    const float* bc1   = (const float*)d_in[14];
    const float* wc2   = (const float*)d_in[15];
    const float* bc2   = (const float*)d_in[16];
    float* out = (float*)d_out;

    prep_kernel<<<NC, 256>>>(w1, b1, g1, beta1, m1, v1,
                             w2, b2, g2, beta2, m2, v2);
    tower_kernel<<<NC * (NB / BPB), 320>>>(x);
    fc1_kernel<<<dim3(2, KSPLIT), 256>>>(wc1);
    fc2_kernel<<<NB, 1024>>>(bc1, wc2, bc2, out);
}